// round 5
// baseline (speedup 1.0000x reference)
#include <cuda_runtime.h>
#include <cstdint>

#define W 512
#define H 512
#define NPLANES 96
#define SKEW 4
#define NWARPS 16
#define CH 16
#define NSTEP_PAD 640          // 512 + 4*31 = 636 -> pad to 40 chunks of 16
#define NCHUNK 40
#define PRO 8                  // consumer chunk k waits producer chunk k+PRO

__device__ __forceinline__ uint32_t smem_u32(const void* p) {
    return (uint32_t)__cvta_generic_to_shared(p);
}

__device__ __forceinline__ void mbar_init(uint32_t a, uint32_t cnt) {
    asm volatile("mbarrier.init.shared.b64 [%0], %1;" :: "r"(a), "r"(cnt) : "memory");
}
__device__ __forceinline__ void mbar_arrive(uint32_t a) {
    asm volatile("mbarrier.arrive.shared.b64 _, [%0];" :: "r"(a) : "memory");
}
// Single-use barrier: wait for its (only) phase-0 completion. HW-sleep, no poll.
__device__ __forceinline__ void mbar_wait0(uint32_t a) {
    uint32_t done;
    asm volatile(
        "{\n\t.reg .pred p;\n\t"
        "mbarrier.try_wait.parity.acquire.cta.shared::cta.b64 p, [%1], 0;\n\t"
        "selp.b32 %0, 1, 0, p;\n\t}"
        : "=r"(done) : "r"(a) : "memory");
    while (!done) {
        asm volatile(
            "{\n\t.reg .pred p;\n\t"
            "mbarrier.try_wait.parity.acquire.cta.shared::cta.b64 p, [%1], 0, 0x989680;\n\t"
            "selp.b32 %0, 1, 0, p;\n\t}"
            : "=r"(done) : "r"(a) : "memory");
    }
}

// One pixel of Floyd-Steinberg (arithmetic byte-identical to the R3 kernel).
__device__ __forceinline__ void px_step(
    float xv, float pv, bool act, int lane, float& left,
    float& r1, float& r2, float& r3, float& r4, float& r5,
    float& outv, float& errv)
{
    const float e_ur = r3, e_u = r4, e_ul = r5;
    float xc = fminf(fmaxf(xv, -1.0f), 1.0f);
    float x01 = __fmul_rn(__fadd_rn(xc, 1.0f), 0.5f);
    float u = __fadd_rn(__fadd_rn(__fmul_rn(0.0625f, e_ul),
                                  __fmul_rn(0.3125f, e_u)),
                        __fmul_rn(0.1875f, e_ur));
    float pre = __fadd_rn(x01, u);
    float raw = __fadd_rn(pre, __fmul_rn(0.4375f, left));
    float val = fminf(fmaxf(raw, 0.0f), 1.0f);
    float d = __fadd_rn(0.5f, -raw);
    unsigned s = (unsigned)(__float_as_int(d) >> 31);
    float err = __fadd_rn(val, __uint_as_float(s & 0xBF800000u));
    err = act ? err : 0.0f;                       // zero padding off the edges
    outv = __uint_as_float(0xBF800000u ^ (s & 0x80000000u));   // 2q-1
    errv = err;
    left = err;
    float sh = __shfl_up_sync(0xFFFFFFFFu, err, 1);
    if (lane == 0) sh = pv;                       // SEL, no branch
    r5 = r4; r4 = r3; r3 = r2; r2 = r1; r1 = sh;
}

// Block = one 512x512 plane, 16 warps; warp w owns rows [32w,32w+32).
// Skew-4 anti-diagonal wavefront in-warp (lane l -> row 32w+l, col c = t-4l);
// skew 4 makes c congruent mod 4 across lanes -> float4 LDG/STG/LDS/STS.
// Band handoff: per-(link,chunk) single-use SMEM mbarriers; producer lane 31
// arrives (release) with unbounded run-ahead, consumer HW-sleeps on try_wait.
__global__ void __launch_bounds__(NWARPS * 32, 1)
fs_dither_kernel(const float* __restrict__ x, float* __restrict__ out) {
    __shared__ __align__(16) float errbuf[NWARPS][W];
    __shared__ __align__(16) float zbuf[W];
    __shared__ uint64_t mbar[NWARPS - 1][NCHUNK];

    const int tid = threadIdx.x;
    const int w = tid >> 5;
    const int lane = tid & 31;
    const int plane = blockIdx.x;

    const float* __restrict__ xp = x + (size_t)plane * (H * W);
    float* __restrict__ op = out + (size_t)plane * (H * W);

    for (int i = tid; i < W; i += NWARPS * 32) zbuf[i] = 0.0f;
    if (tid == 0) {
        uint32_t base = smem_u32(&mbar[0][0]);
        for (int i = 0; i < (NWARPS - 1) * NCHUNK; ++i)
            mbar_init(base + 8u * i, 1u);
    }
    __syncthreads();

    const float* __restrict__ prevrow = (w == 0) ? zbuf : errbuf[w - 1];
    float* __restrict__ myrow = errbuf[w];
    const int row = w * 32 + lane;
    const float* __restrict__ xrow = xp + (size_t)row * W;
    float* __restrict__ orow = op + (size_t)row * W;

    // Delay line: at start of step t (lane 0 view) r1=prev[t+3], r2=prev[t+2],
    // r3=prev[t+1] (e_ur), r4=prev[t] (e_u), r5=prev[t-1] (e_ul).
    float r1 = 0.0f, r2 = 0.0f, r3 = 0.0f, r4 = 0.0f, r5 = 0.0f;
    float left = 0.0f;

    int t = 0;
    for (int k = 0; k < NCHUNK; ++k) {
        if (w != 0 && k <= NCHUNK - 1 - PRO) {
            mbar_wait0(smem_u32(&mbar[w - 1][k + PRO]));   // acquire
            __syncwarp();
            if (k == 0) {
                // seed lane-0 delay line from the just-published prev row
                float4 p0 = *(const float4*)prevrow;        // cols 0..3
                if (lane == 0) { r4 = p0.x; r3 = p0.y; r2 = p0.z; r1 = p0.w; }
            }
        }

        #pragma unroll
        for (int m = 0; m < CH / 4; ++m) {
            const int cb = t - SKEW * lane;            // multiple of 4
            const bool act = ((unsigned)cb) < (unsigned)W;
            float4 xq = make_float4(-1.0f, -1.0f, -1.0f, -1.0f);
            if (act) xq = *(const float4*)(xrow + cb);
            const int pb = t + SKEW;                   // multiple of 4
            float4 pq = make_float4(0.0f, 0.0f, 0.0f, 0.0f);
            if (pb < W) pq = *(const float4*)(prevrow + pb);   // LDS.128 bcast

            float4 oq, eq;
            px_step(xq.x, pq.x, act, lane, left, r1, r2, r3, r4, r5, oq.x, eq.x);
            px_step(xq.y, pq.y, act, lane, left, r1, r2, r3, r4, r5, oq.y, eq.y);
            px_step(xq.z, pq.z, act, lane, left, r1, r2, r3, r4, r5, oq.z, eq.z);
            px_step(xq.w, pq.w, act, lane, left, r1, r2, r3, r4, r5, oq.w, eq.w);

            if (act) *(float4*)(orow + cb) = oq;                  // STG.128
            if (act & (lane == 31)) *(float4*)(myrow + cb) = eq;  // STS.128
            t += 4;
        }

        if (w != NWARPS - 1 && lane == 31)
            mbar_arrive(smem_u32(&mbar[w][k]));        // release (lane31's STS)
    }
}

extern "C" void kernel_launch(void* const* d_in, const int* in_sizes, int n_in,
                              void* d_out, int out_size) {
    (void)in_sizes; (void)n_in; (void)out_size;
    const float* x = (const float*)d_in[0];
    float* out = (float*)d_out;
    fs_dither_kernel<<<NPLANES, NWARPS * 32>>>(x, out);
}

// round 6
// speedup vs baseline: 1.4312x; 1.4312x over previous
#include <cuda_runtime.h>

#define W 512
#define H 512
#define NPLANES 96
#define SKEW 3
#define NWARPS 16
#define CH 16
#define LAG 96            // 32 rows * SKEW
#define NSTEP_PAD 608     // 512 + 3*31 = 605, padded to 38 chunks of 16
#define NCHUNK 38
#define KLO 6             // first chunk with all 32 lanes active (t0=96 >= 93)
#define KHI 31            // last chunk with all lanes active (t0=496, ends 511)
#define ROWP 516          // err row padded so steady prev reads (<=514) need no guard

__device__ __forceinline__ float clip01(float xv) {
    // x = clip(x,-1,1); x01 = (x+1)/2   (exact, matches reference)
    xv = fminf(fmaxf(xv, -1.0f), 1.0f);
    return __fmul_rn(__fadd_rn(xv, 1.0f), 0.5f);
}

// One steady chunk: 16 guard-free steps, inputs pre-clipped in registers,
// prev row batch-preloaded, next chunk's inputs prefetched (double buffer).
template<bool LOAD_NEXT>
__device__ __forceinline__ void steady_chunk(
    int t0, int lane,
    const float* __restrict__ xrow,
    float (&cur)[CH], float (&nxt)[CH],
    const float* __restrict__ prevrow,
    float* __restrict__ orow, float* __restrict__ myrow,
    float& left, float& r1, float& r2, float& r3, float& r4)
{
    const int cb = t0 - SKEW * lane;        // this lane's base column (>=3)
    if (LOAD_NEXT) {
        #pragma unroll
        for (int i = 0; i < CH; ++i)
            nxt[i] = clip01(__ldg(xrow + cb + CH + i));   // batched, MLP=16
    }
    float ps[CH];
    #pragma unroll
    for (int i = 0; i < CH; ++i) ps[i] = prevrow[t0 + SKEW + i];  // bcast LDS
    const bool is31 = (lane == 31);

    #pragma unroll
    for (int i = 0; i < CH; ++i) {
        const float e_ur = r2, e_u = r3, e_ul = r4;
        // up = (1/16*e_ul + 5/16*e_u) + 3/16*e_ur  (reference order, no FMA)
        float u = __fadd_rn(__fadd_rn(__fmul_rn(0.0625f, e_ul),
                                      __fmul_rn(0.3125f, e_u)),
                            __fmul_rn(0.1875f, e_ur));
        float pre = __fadd_rn(cur[i], u);
        float raw = __fadd_rn(pre, __fmul_rn(0.4375f, left));
        float val = fminf(fmaxf(raw, 0.0f), 1.0f);
        // q = round-half-even(val) <=> raw > 0.5; sign of 0.5-raw is exact.
        float d = __fadd_rn(0.5f, -raw);
        unsigned s = (unsigned)(__float_as_int(d) >> 31);
        float err = __fadd_rn(val, __uint_as_float(s & 0xBF800000u));
        __stcs(orow + cb + i, __uint_as_float(0xBF800000u ^ (s & 0x80000000u)));
        if (is31) myrow[cb + i] = err;      // hand off to next band
        left = err;
        float sh = __shfl_up_sync(0xFFFFFFFFu, err, 1);
        if (lane == 0) sh = ps[i];          // SEL, no branch
        r4 = r3; r3 = r2; r2 = r1; r1 = sh;
    }
}

// Block = one 512x512 plane, 16 warps; warp w owns rows [32w, 32w+32).
// In-warp: skew-3 anti-diagonal wavefront (lane l -> row 32w+l, col c = t-3l).
// Across warps: chunked SMEM err-row handoff with volatile progress counters
// (plain spin: R4/R5 showed nanosleep / mbarrier waits regress the fill cascade).
__global__ void __launch_bounds__(NWARPS * 32, 1)
fs_dither_kernel(const float* __restrict__ x, float* __restrict__ out) {
    __shared__ float errbuf[NWARPS][ROWP];
    __shared__ float zbuf[ROWP];
    __shared__ volatile unsigned progress[NWARPS];

    const int tid = threadIdx.x;
    const int w = tid >> 5;
    const int lane = tid & 31;
    const int plane = blockIdx.x;

    const float* __restrict__ xp = x + (size_t)plane * (H * W);
    float* __restrict__ op = out + (size_t)plane * (H * W);

    for (int i = tid; i < NWARPS * ROWP; i += NWARPS * 32)
        (&errbuf[0][0])[i] = 0.0f;                  // zero incl. pad columns
    for (int i = tid; i < ROWP; i += NWARPS * 32) zbuf[i] = 0.0f;
    if (tid < NWARPS) progress[tid] = 0u;
    __syncthreads();

    const float* __restrict__ prevrow = (w == 0) ? zbuf : errbuf[w - 1];
    float* __restrict__ myrow = errbuf[w];
    const int row = w * 32 + lane;
    const float* __restrict__ xrow = xp + (size_t)row * W;
    float* __restrict__ orow = op + (size_t)row * W;

    // Delay line: at step t lane l consumes e_ur=r2, e_u=r3, e_ul=r4 (row-above
    // errs at cols c+1, c, c-1); r1 is the 3-ahead value (lane0: prevrow[t+3]).
    float r1 = 0.0f, r2 = 0.0f, r3 = 0.0f, r4 = 0.0f;
    float left = 0.0f;
    float xs0[CH], xs1[CH];

    int t = 0;
    for (int k = 0; k < NCHUNK; ++k) {
        if (w != 0) {
            unsigned need = (unsigned)(t + CH + LAG);
            if (need > NSTEP_PAD) need = NSTEP_PAD;
            while (progress[w - 1] < need) { /* spin (proven fastest) */ }
        }
        __syncwarp();
        __threadfence_block();   // acquire: producer's STS now visible

        if (k == 0 && lane == 0) {
            r4 = 0.0f;            // prev[-1] (pad)
            r3 = prevrow[0];
            r2 = prevrow[1];
            r1 = prevrow[2];
        }

        if (k >= KLO && k <= KHI) {
            if (k == KLO) {       // prime the double buffer (one-time)
                const int cb = t - SKEW * lane;
                #pragma unroll
                for (int i = 0; i < CH; ++i)
                    xs0[i] = clip01(__ldg(xrow + cb + i));
            }
            if (((k - KLO) & 1) == 0) {
                if (k < KHI) steady_chunk<true >(t, lane, xrow, xs0, xs1, prevrow, orow, myrow, left, r1, r2, r3, r4);
                else         steady_chunk<false>(t, lane, xrow, xs0, xs1, prevrow, orow, myrow, left, r1, r2, r3, r4);
            } else {
                if (k < KHI) steady_chunk<true >(t, lane, xrow, xs1, xs0, prevrow, orow, myrow, left, r1, r2, r3, r4);
                else         steady_chunk<false>(t, lane, xrow, xs1, xs0, prevrow, orow, myrow, left, r1, r2, r3, r4);
            }
            t += CH;
        } else {
            // Ramp chunks: R3 guarded body (some lanes inactive).
            #pragma unroll 4
            for (int i = 0; i < CH; ++i, ++t) {
                const int c = t - SKEW * lane;
                const bool active = ((unsigned)c < (unsigned)W);
                const float e_ur = r2, e_u = r3, e_ul = r4;

                int cl = c < 0 ? 0 : (c > W - 1 ? W - 1 : c);
                float x01 = clip01(__ldg(xrow + cl));

                float u = __fadd_rn(__fadd_rn(__fmul_rn(0.0625f, e_ul),
                                              __fmul_rn(0.3125f, e_u)),
                                    __fmul_rn(0.1875f, e_ur));
                float pre = __fadd_rn(x01, u);
                float raw = __fadd_rn(pre, __fmul_rn(0.4375f, left));
                float val = fminf(fmaxf(raw, 0.0f), 1.0f);
                float d = __fadd_rn(0.5f, -raw);
                unsigned s = (unsigned)(__float_as_int(d) >> 31);
                float err = __fadd_rn(val, __uint_as_float(s & 0xBF800000u));
                err = active ? err : 0.0f;        // zero padding off the edges

                if (active) {
                    __stcs(orow + c, __uint_as_float(0xBF800000u ^ (s & 0x80000000u)));
                    if (lane == 31) myrow[c] = err;
                }
                left = err;

                float sh = __shfl_up_sync(0xFFFFFFFFu, err, 1);
                const int pi = t + SKEW;
                float pv = (pi < W) ? prevrow[pi] : 0.0f;
                if (lane == 0) sh = pv;
                r4 = r3; r3 = r2; r2 = r1; r1 = sh;
            }
        }

        if (lane == 31) {
            __threadfence_block();     // release: STS before counter
            progress[w] = (unsigned)t;
        }
    }
}

extern "C" void kernel_launch(void* const* d_in, const int* in_sizes, int n_in,
                              void* d_out, int out_size) {
    (void)in_sizes; (void)n_in; (void)out_size;
    const float* x = (const float*)d_in[0];
    float* out = (float*)d_out;
    fs_dither_kernel<<<NPLANES, NWARPS * 32>>>(x, out);
}